// round 17
// baseline (speedup 1.0000x reference)
#include <cuda_runtime.h>
#include <cstdint>

// Spiking1DLIFLayer: B=128, C=512, T=1024  (row=(b,c), serial recurrence over T)
//   mem = (mem*beta + x[t]) - spk_prev*Vth[c] ;  spk = mem > Vth[c]
// Pure HBM-bound stream (256MB in + 256MB out).
//
// R17: MINIMAL SMSP SPREAD of the R10 winner (92.3us). Profile shows 7
// single-warp blocks/SM all map to SMSP0 (wid%4): issue 21.7% avg == ~87% on
// one scheduler, ~0 on the other three; 512B store bursts (32x STG.128 @
// ~12cyc issue) nearly fill each group window on that port. This round: two
// FULLY INDEPENDENT per-warp pipelines per 64-thread block (own NBUF=3 input
// ring, own GROUP=4 fp32 acc, __syncwarp only) -> 3 blocks/SM = 6 warps on 2
// schedulers (~45% each). Per-warp code byte-identical to R10: cp.async.cg
// triple-buffer, 512B write-through bursts (wt = only policy avoiding the
// ~15us replay-boundary dirty-L2 drain). R11's failed spread changed NBUF/
// grid/regs simultaneously; this changes ONLY the warp->SMSP mapping.
// Numerics bit-identical to reference (rel_err 0.0 in R1-R16).

#define Bdim 128
#define Cdim 512
#define Tdim 1024
#define NT    64                 // 2 warps per block, independent pipelines
#define WARPS 2
#define RPW   32                 // rows per warp (lane == row)
#define TS    32                 // time-tile (floats)
#define F4    (TS / 4)           // 8 float4 per row per tile
#define PITCH (F4 + 1)           // 9 -> conflict-free input-buf access
#define NBUF  3
#define NTILES (Tdim / TS)       // 32
#define GROUP 4                  // tiles per write burst (4*128B = 512B/row)
#define ACC_F4 (GROUP * F4)      // 32 float4 per row in accumulator
#define ACC_PITCH (ACC_F4 + 1)   // 33

__device__ __forceinline__ void cp16(uint32_t dst_smem, const float4* src) {
    asm volatile("cp.async.cg.shared.global [%0], [%1], 16;\n"
                 :: "r"(dst_smem), "l"(src));
}
__device__ __forceinline__ void cp_commit() {
    asm volatile("cp.async.commit_group;\n");
}
__device__ __forceinline__ void cp_wait2() {
    asm volatile("cp.async.wait_group 2;\n");
}
__device__ __forceinline__ void stwt(float4* p, float4 v) {
    asm volatile("st.global.wt.v4.f32 [%0], {%1, %2, %3, %4};\n"
                 :: "l"(p), "f"(v.x), "f"(v.y), "f"(v.z), "f"(v.w)
                 : "memory");
}

__global__ void __launch_bounds__(NT, 3)
lif_kernel(const float* __restrict__ x,
           const float* __restrict__ beta_p,
           const float* __restrict__ vth_p,
           float* __restrict__ out)
{
    // per-warp private regions (static smem, warp-indexed)
    __shared__ float4 tile[WARPS][NBUF][RPW * PITCH];  // 2 x 13.5 KB
    __shared__ float4 acc[WARPS][RPW * ACC_PITCH];     // 2 x 16.9 KB

    const int tid  = threadIdx.x;
    const int w    = tid >> 5;                    // warp id -> SMSP w
    const int lane = tid & 31;
    const int r0   = blockIdx.x * NT + w * RPW;   // first row of this warp

    const float beta = __ldg(beta_p);
    const float vth  = __ldg(vth_p + ((r0 + lane) & (Cdim - 1)));

    const float4* __restrict__ xg = (const float4*)x;
    float4* __restrict__ og = (float4*)out;
    const int row_f4 = Tdim / 4;                  // 256 float4 per global row

    // ---- prologue: preload tiles 0..2 into this warp's ring ----
    #pragma unroll
    for (int p = 0; p < NBUF; ++p) {
        const int tcol0 = p * F4;
        uint32_t sbase = (uint32_t)__cvta_generic_to_shared(&tile[w][p][0]);
        #pragma unroll
        for (int i = 0; i < F4; ++i) {
            int idx = i * RPW + lane;
            int row = idx >> 3;                   // idx / F4
            int col = idx & 7;                    // idx % F4
            cp16(sbase + (uint32_t)(row * PITCH + col) * 16u,
                 xg + (size_t)(r0 + row) * row_f4 + tcol0 + col);
        }
        cp_commit();
    }

    float mem = 0.0f;
    float rst = 0.0f;
    int b = 0;

    for (int it = 0; it < NTILES; ++it) {
        cp_wait2();                               // this warp's tile `it` landed
        __syncwarp();                             // intra-warp visibility

        // ---- recurrence: lane owns row, 32 steps ----
        float4* mybuf = &tile[w][b][lane * PITCH];
        float4* myacc = &acc[w][lane * ACC_PITCH + (it & (GROUP - 1)) * F4];
        #pragma unroll
        for (int c = 0; c < F4; ++c) {
            float4 v = mybuf[c];
            float4 s;
            #define LIF_STEP(XV, SV)                                   \
                do {                                                   \
                    float t1 = __fmul_rn(mem, beta);                   \
                    float t2 = __fadd_rn(t1, (XV));                    \
                    mem = __fadd_rn(t2, -rst);                         \
                    float spk = (mem > vth) ? 1.0f : 0.0f;             \
                    (SV) = spk;                                        \
                    rst = (mem > vth) ? vth : 0.0f;                    \
                } while (0)
            LIF_STEP(v.x, s.x);
            LIF_STEP(v.y, s.y);
            LIF_STEP(v.z, s.z);
            LIF_STEP(v.w, s.w);
            #undef LIF_STEP
            myacc[c] = s;
        }
        __syncwarp();      // tile[w][b] fully consumed + acc visible cross-lane

        // ---- refill buf b with tile it+3 (reads in flight during flush);
        //      always commit one group per iteration ----
        const int ip = it + NBUF;
        if (ip < NTILES) {
            const int tcol0 = ip * F4;
            uint32_t sbase = (uint32_t)__cvta_generic_to_shared(&tile[w][b][0]);
            #pragma unroll
            for (int i = 0; i < F4; ++i) {
                int idx = i * RPW + lane;
                int row = idx >> 3;
                int col = idx & 7;
                cp16(sbase + (uint32_t)(row * PITCH + col) * 16u,
                     xg + (size_t)(r0 + row) * row_f4 + tcol0 + col);
            }
        }
        cp_commit();

        // ---- every GROUP tiles: flush 512B/row write-through bursts ----
        if ((it & (GROUP - 1)) == (GROUP - 1)) {
            const int tbase = (it - (GROUP - 1)) * F4;   // first f4 col of group
            #pragma unroll
            for (int i = 0; i < RPW; ++i) {
                // one warp-instruction per row: lanes cover 32 consecutive f4
                stwt(og + (size_t)(r0 + i) * row_f4 + tbase + lane,
                     acc[w][i * ACC_PITCH + lane]);
            }
        }

        b = (b == NBUF - 1) ? 0 : b + 1;
    }
}

extern "C" void kernel_launch(void* const* d_in, const int* in_sizes, int n_in,
                              void* d_out, int out_size)
{
    const float* x    = (const float*)d_in[0];  // (128, 512, 1024) fp32
    const float* beta = (const float*)d_in[1];  // scalar fp32
    const float* vth  = (const float*)d_in[2];  // (512,) fp32
    float* out        = (float*)d_out;          // (128, 512, 1024) fp32

    lif_kernel<<<(Bdim * Cdim) / NT, NT>>>(x, beta, vth, out);
}